// round 3
// baseline (speedup 1.0000x reference)
#include <cuda_runtime.h>

typedef unsigned long long u64;

#define B_   256
#define T_   2048
#define DIN  64
#define H_   32
#define C_   16
#define R_   (B_ * T_)

// Scratch (allocation-free rule: __device__ globals)
__device__ float g_u[(size_t)R_ * H_];    // x@W_in^T + b_in + b_res_enc
__device__ float g_dec[(size_t)R_ * H_];  // decoder hidden states

// ---------------- packed f32x2 helpers (Blackwell FFMA2) ----------------
__device__ __forceinline__ u64 fma2(u64 a, u64 b, u64 c) {
    u64 d;
    asm("fma.rn.f32x2 %0, %1, %2, %3;" : "=l"(d) : "l"(a), "l"(b), "l"(c));
    return d;
}
__device__ __forceinline__ u64 add2(u64 a, u64 b) {
    u64 d;
    asm("add.rn.f32x2 %0, %1, %2;" : "=l"(d) : "l"(a), "l"(b));
    return d;
}
__device__ __forceinline__ u64 pack2(float lo, float hi) {
    u64 r;
    asm("mov.b64 %0, {%1, %2};" : "=l"(r) : "f"(lo), "f"(hi));
    return r;
}
__device__ __forceinline__ float unpack_sum(u64 v) {
    float lo, hi;
    asm("mov.b64 {%0, %1}, %2;" : "=f"(lo), "=f"(hi) : "l"(v));
    return lo + hi;
}
__device__ __forceinline__ float hsum4(u64 a0, u64 a1, u64 a2, u64 a3) {
    return unpack_sum(add2(add2(a0, a1), add2(a2, a3)));
}
// accurate-enough tanh: __expf rel err ~1e-7, safe for the 1e-3 gate
__device__ __forceinline__ float tanh_acc(float x) {
    x = fminf(15.0f, fmaxf(-15.0f, x));
    float e = __expf(2.0f * x);
    return __fdividef(e - 1.0f, e + 1.0f);
}

// ---------------- Kernel 1: u = x @ W_in^T + (b_in + b_res_enc) ----------------
__global__ void __launch_bounds__(256) k_proj_in(const float* __restrict__ x,
                                                 const float* __restrict__ Win,
                                                 const float* __restrict__ bin,
                                                 const float* __restrict__ brese) {
    __shared__ __align__(16) float shx[8][2][DIN];
    const int lane = threadIdx.x & 31;
    const int wl   = threadIdx.x >> 5;
    const int w    = blockIdx.x * (blockDim.x >> 5) + wl;
    const int nw   = gridDim.x * (blockDim.x >> 5);

    // lane's W_in row (h = lane), packed over d
    u64 Wr[DIN / 2];
    const u64* wrow = reinterpret_cast<const u64*>(Win + lane * DIN);
#pragma unroll
    for (int k = 0; k < DIN / 2; k++) Wr[k] = wrow[k];
    const float bias = bin[lane] + brese[lane];

    int p = 0;
    for (int row = w; row < R_; row += nw) {
        const float2* xr = reinterpret_cast<const float2*>(x + (size_t)row * DIN);
        reinterpret_cast<float2*>(shx[wl][p])[lane] = xr[lane];
        __syncwarp();
        const ulonglong2* hp = reinterpret_cast<const ulonglong2*>(shx[wl][p]);
        u64 a0 = 0, a1 = 0, a2 = 0, a3 = 0;
#pragma unroll
        for (int k = 0; k < 16; k += 2) {
            ulonglong2 v0 = hp[k];
            ulonglong2 v1 = hp[k + 1];
            a0 = fma2(Wr[2 * k],     v0.x, a0);
            a1 = fma2(Wr[2 * k + 1], v0.y, a1);
            a2 = fma2(Wr[2 * k + 2], v1.x, a2);
            a3 = fma2(Wr[2 * k + 3], v1.y, a3);
        }
        g_u[(size_t)row * H_ + lane] = bias + hsum4(a0, a1, a2, a3);
        p ^= 1;
    }
}

// ---------------- Kernel 2: fused dual ESN scan (1 warp per batch chain) ----------------
__global__ void __launch_bounds__(32) k_scan(const float* __restrict__ Wenc_g,
                                             const float* __restrict__ Wdec_g,
                                             const float* __restrict__ Wcode,
                                             const float* __restrict__ bcode,
                                             const float* __restrict__ Wco,
                                             const float* __restrict__ bco,
                                             const float* __restrict__ bresd) {
    const int lane = threadIdx.x;
    const int b    = blockIdx.x;
    __shared__ __align__(16) float she[2][H_];
    __shared__ __align__(16) float shd[2][H_];

    // weights, packed along j (columns)
    u64 We[16], Wd[16], Mm[16];
    {
        const u64* a = reinterpret_cast<const u64*>(Wenc_g + lane * H_);
        const u64* d = reinterpret_cast<const u64*>(Wdec_g + lane * H_);
#pragma unroll
        for (int k = 0; k < 16; k++) { We[k] = a[k]; Wd[k] = d[k]; }
    }
    float btot = bco[lane] + bresd[lane];
    {
        float wc[C_];
#pragma unroll
        for (int c = 0; c < C_; c++) {
            wc[c] = Wco[lane * C_ + c];
            btot  = fmaf(wc[c], bcode[c], btot);
        }
        // M = W_co @ W_code (row = lane), packed over j
#pragma unroll
        for (int k = 0; k < 16; k++) {
            u64 m = 0;
#pragma unroll
            for (int c = 0; c < C_; c++) {
                m = fma2(pack2(wc[c], wc[c]),
                         reinterpret_cast<const u64*>(Wcode + c * H_)[k], m);
            }
            Mm[k] = m;
        }
    }

    // replicated hidden states as packed pairs {h[2k], h[2k+1]}; zero-init
    u64 he[16], hd[16];
#pragma unroll
    for (int k = 0; k < 16; k++) { he[k] = 0ull; hd[k] = 0ull; }

    const float* up = g_u + ((size_t)b * T_) * H_ + lane;
    float*       dp = g_dec + ((size_t)b * T_) * H_ + lane;

    // 4-deep prefetch ring for u (DRAM latency cover)
    float ur[4];
#pragma unroll
    for (int i = 0; i < 4; i++) ur[i] = up[(size_t)i * H_];

    int p = 0;
    for (int t = 0; t < T_; t += 4) {
#pragma unroll
        for (int i = 0; i < 4; i++) {
            const float u = ur[i];
            const int tn  = t + 4 + i;
            ur[i] = up[(size_t)((tn < T_) ? tn : 0) * H_];

            // decoder recurrent partial (independent of this step's encoder)
            u64 d0 = 0, d1 = 0, d2 = 0, d3 = 0;
#pragma unroll
            for (int k = 0; k < 16; k += 4) {
                d0 = fma2(Wd[k],     hd[k],     d0);
                d1 = fma2(Wd[k + 1], hd[k + 1], d1);
                d2 = fma2(Wd[k + 2], hd[k + 2], d2);
                d3 = fma2(Wd[k + 3], hd[k + 3], d3);
            }
            // encoder matvec
            u64 a0 = 0, a1 = 0, a2 = 0, a3 = 0;
#pragma unroll
            for (int k = 0; k < 16; k += 4) {
                a0 = fma2(We[k],     he[k],     a0);
                a1 = fma2(We[k + 1], he[k + 1], a1);
                a2 = fma2(We[k + 2], he[k + 2], a2);
                a3 = fma2(We[k + 3], he[k + 3], a3);
            }
            const float hE = tanh_acc(u + hsum4(a0, a1, a2, a3));

            // replicate h_enc (broadcast LDS.128 -> packed pairs for free)
            she[p][lane] = hE;
            __syncwarp();
            {
                const ulonglong2* q = reinterpret_cast<const ulonglong2*>(she[p]);
#pragma unroll
                for (int k = 0; k < 8; k++) {
                    ulonglong2 v = q[k];
                    he[2 * k] = v.x;
                    he[2 * k + 1] = v.y;
                }
            }
            // v = M h_enc
            u64 m0 = 0, m1 = 0, m2 = 0, m3 = 0;
#pragma unroll
            for (int k = 0; k < 16; k += 4) {
                m0 = fma2(Mm[k],     he[k],     m0);
                m1 = fma2(Mm[k + 1], he[k + 1], m1);
                m2 = fma2(Mm[k + 2], he[k + 2], m2);
                m3 = fma2(Mm[k + 3], he[k + 3], m3);
            }
            const float hD = tanh_acc(btot + hsum4(m0, m1, m2, m3) + hsum4(d0, d1, d2, d3));

            // replicate h_dec
            shd[p][lane] = hD;
            __syncwarp();
            {
                const ulonglong2* q = reinterpret_cast<const ulonglong2*>(shd[p]);
#pragma unroll
                for (int k = 0; k < 8; k++) {
                    ulonglong2 v = q[k];
                    hd[2 * k] = v.x;
                    hd[2 * k + 1] = v.y;
                }
            }
            dp[(size_t)(t + i) * H_] = hD;
            p ^= 1;
        }
    }
}

// ---------------- Kernel 3: out = dec @ W_ro^T + b_ro ----------------
__global__ void __launch_bounds__(256) k_proj_out(const float* __restrict__ Wro,
                                                  const float* __restrict__ bro,
                                                  float* __restrict__ out) {
    __shared__ __align__(16) float shh[8][2][H_];
    const int lane = threadIdx.x & 31;
    const int wl   = threadIdx.x >> 5;
    const int w    = blockIdx.x * (blockDim.x >> 5) + wl;
    const int nw   = gridDim.x * (blockDim.x >> 5);

    // lane handles output dims lane and lane+32
    u64 W0[16], W1[16];
    {
        const u64* r0 = reinterpret_cast<const u64*>(Wro + lane * H_);
        const u64* r1 = reinterpret_cast<const u64*>(Wro + (lane + 32) * H_);
#pragma unroll
        for (int k = 0; k < 16; k++) { W0[k] = r0[k]; W1[k] = r1[k]; }
    }
    const float c0 = bro[lane];
    const float c1 = bro[lane + 32];

    int p = 0;
    for (int row = w; row < R_; row += nw) {
        shh[wl][p][lane] = g_dec[(size_t)row * H_ + lane];
        __syncwarp();
        const ulonglong2* hp = reinterpret_cast<const ulonglong2*>(shh[wl][p]);
        u64 a0 = 0, a1 = 0, b0 = 0, b1 = 0;
#pragma unroll
        for (int k = 0; k < 8; k++) {
            ulonglong2 v = hp[k];
            a0 = fma2(W0[2 * k],     v.x, a0);
            a1 = fma2(W0[2 * k + 1], v.y, a1);
            b0 = fma2(W1[2 * k],     v.x, b0);
            b1 = fma2(W1[2 * k + 1], v.y, b1);
        }
        out[(size_t)row * DIN + lane]      = c0 + unpack_sum(add2(a0, a1));
        out[(size_t)row * DIN + 32 + lane] = c1 + unpack_sum(add2(b0, b1));
        p ^= 1;
    }
}

// ---------------- launch ----------------
extern "C" void kernel_launch(void* const* d_in, const int* in_sizes, int n_in,
                              void* d_out, int out_size) {
    const float* x     = (const float*)d_in[0];
    const float* Win   = (const float*)d_in[1];
    const float* bin   = (const float*)d_in[2];
    const float* Wrese = (const float*)d_in[3];
    const float* brese = (const float*)d_in[4];
    const float* Wcode = (const float*)d_in[5];
    const float* bcode = (const float*)d_in[6];
    const float* Wco   = (const float*)d_in[7];
    const float* bco   = (const float*)d_in[8];
    const float* Wresd = (const float*)d_in[9];
    const float* bresd = (const float*)d_in[10];
    const float* Wro   = (const float*)d_in[11];
    const float* bro   = (const float*)d_in[12];
    float* out = (float*)d_out;

    k_proj_in<<<2048, 256>>>(x, Win, bin, brese);
    k_scan<<<B_, 32>>>(Wrese, Wresd, Wcode, bcode, Wco, bco, bresd);
    k_proj_out<<<2048, 256>>>(Wro, bro, out);
}

// round 4
// speedup vs baseline: 1.2175x; 1.2175x over previous
#include <cuda_runtime.h>

typedef unsigned long long u64;

#define B_   256
#define T_   2048
#define DIN  64
#define H_   32
#define C_   16
#define R_   (B_ * T_)

// Scratch (allocation-free rule: __device__ globals)
__device__ float g_u[(size_t)R_ * H_];    // x@W_in^T + b_in + b_res_enc
__device__ float g_dec[(size_t)R_ * H_];  // decoder hidden states

#define FENCE() asm volatile("" ::: "memory")

// ---------------- packed f32x2 helpers (Blackwell FFMA2) ----------------
__device__ __forceinline__ u64 fma2(u64 a, u64 b, u64 c) {
    u64 d;
    asm("fma.rn.f32x2 %0, %1, %2, %3;" : "=l"(d) : "l"(a), "l"(b), "l"(c));
    return d;
}
__device__ __forceinline__ u64 add2(u64 a, u64 b) {
    u64 d;
    asm("add.rn.f32x2 %0, %1, %2;" : "=l"(d) : "l"(a), "l"(b));
    return d;
}
__device__ __forceinline__ u64 pack2(float lo, float hi) {
    u64 r;
    asm("mov.b64 %0, {%1, %2};" : "=l"(r) : "f"(lo), "f"(hi));
    return r;
}
__device__ __forceinline__ float unpack_sum(u64 v) {
    float lo, hi;
    asm("mov.b64 {%0, %1}, %2;" : "=f"(lo), "=f"(hi) : "l"(v));
    return lo + hi;
}
__device__ __forceinline__ float hsum4(u64 a0, u64 a1, u64 a2, u64 a3) {
    return unpack_sum(add2(add2(a0, a1), add2(a2, a3)));
}
// tanh = 1 - 2/(1+e^{2x}); e^{2x}: 0 -> -1, inf -> +1, no NaN path, no clamps
__device__ __forceinline__ float tanh_fast(float x) {
    float e = __expf(2.0f * x);
    return 1.0f - __fdividef(2.0f, 1.0f + e);
}

// ---------------- Kernel 1: u = x @ W_in^T + (b_in + b_res_enc) ----------------
// Tiled: 64 rows/tile staged in smem (double-buffered), one __syncthreads per
// tile, NO per-row warp sync. Each of 8 warps handles 8 rows; lane = h index.
#define K1_TILE 64
#define K1_NT   (R_ / K1_TILE)     // 8192
#define K1_GRID 2048
__global__ void __launch_bounds__(256) k_proj_in(const float* __restrict__ x,
                                                 const float* __restrict__ Win,
                                                 const float* __restrict__ bin,
                                                 const float* __restrict__ brese) {
    __shared__ __align__(16) float4 sh[2][K1_TILE * DIN / 4];   // 2 x 16KB
    const int tid  = threadIdx.x;
    const int lane = tid & 31;
    const int w    = tid >> 5;

    u64 Wr[DIN / 2];
    const u64* wrow = reinterpret_cast<const u64*>(Win + lane * DIN);
#pragma unroll
    for (int k = 0; k < DIN / 2; k++) Wr[k] = wrow[k];
    const float bias = bin[lane] + brese[lane];

    const float4* x4 = reinterpret_cast<const float4*>(x);

    int tile = blockIdx.x;
    // prologue: load tile into buf 0
    {
        const float4* src = x4 + (size_t)tile * (K1_TILE * DIN / 4);
#pragma unroll
        for (int k = 0; k < 4; k++) sh[0][tid + k * 256] = src[tid + k * 256];
    }
    __syncthreads();

    int p = 0;
    while (tile < K1_NT) {
        const int nt = tile + K1_GRID;
        float4 n0, n1, n2, n3;
        if (nt < K1_NT) {
            const float4* src = x4 + (size_t)nt * (K1_TILE * DIN / 4);
            n0 = src[tid];       n1 = src[tid + 256];
            n2 = src[tid + 512]; n3 = src[tid + 768];
        }
        // compute 8 rows per warp from buf p
#pragma unroll
        for (int r = 0; r < 8; r++) {
            const int lrow = w * 8 + r;
            const ulonglong2* hp =
                reinterpret_cast<const ulonglong2*>(&sh[p][lrow * (DIN / 4)]);
            u64 a0 = 0, a1 = 0, a2 = 0, a3 = 0;
#pragma unroll
            for (int k = 0; k < 16; k += 2) {
                ulonglong2 v0 = hp[k];
                ulonglong2 v1 = hp[k + 1];
                a0 = fma2(Wr[2 * k],     v0.x, a0);
                a1 = fma2(Wr[2 * k + 1], v0.y, a1);
                a2 = fma2(Wr[2 * k + 2], v1.x, a2);
                a3 = fma2(Wr[2 * k + 3], v1.y, a3);
            }
            g_u[(size_t)(tile * K1_TILE + lrow) * H_ + lane] = bias + hsum4(a0, a1, a2, a3);
        }
        if (nt < K1_NT) {
            sh[p ^ 1][tid]       = n0; sh[p ^ 1][tid + 256] = n1;
            sh[p ^ 1][tid + 512] = n2; sh[p ^ 1][tid + 768] = n3;
        }
        __syncthreads();
        p ^= 1;
        tile = nt;
    }
}

// ---------------- Kernel 2: fused dual ESN scan (1 warp per batch chain) ----------------
// No __syncwarp: single warp, no divergence; smem STS->LDS is in-order through
// the MIO pipe; compiler fences stop reordering. Short tanh, dec-partial first.
__global__ void __launch_bounds__(32) k_scan(const float* __restrict__ Wenc_g,
                                             const float* __restrict__ Wdec_g,
                                             const float* __restrict__ Wcode,
                                             const float* __restrict__ bcode,
                                             const float* __restrict__ Wco,
                                             const float* __restrict__ bco,
                                             const float* __restrict__ bresd) {
    const int lane = threadIdx.x;
    const int b    = blockIdx.x;
    __shared__ __align__(16) float she[H_];
    __shared__ __align__(16) float shd[H_];

    // weights, packed along j (columns)
    u64 We[16], Wd[16], Mm[16];
    {
        const u64* a = reinterpret_cast<const u64*>(Wenc_g + lane * H_);
        const u64* d = reinterpret_cast<const u64*>(Wdec_g + lane * H_);
#pragma unroll
        for (int k = 0; k < 16; k++) { We[k] = a[k]; Wd[k] = d[k]; }
    }
    float btot = bco[lane] + bresd[lane];
    {
        float wc[C_];
#pragma unroll
        for (int c = 0; c < C_; c++) {
            wc[c] = Wco[lane * C_ + c];
            btot  = fmaf(wc[c], bcode[c], btot);
        }
        // M = W_co @ W_code (row = lane), packed over j
#pragma unroll
        for (int k = 0; k < 16; k++) {
            u64 m = 0;
#pragma unroll
            for (int c = 0; c < C_; c++) {
                m = fma2(pack2(wc[c], wc[c]),
                         reinterpret_cast<const u64*>(Wcode + c * H_)[k], m);
            }
            Mm[k] = m;
        }
    }

    // replicated hidden states as packed pairs {h[2k], h[2k+1]}; zero-init
    u64 he[16], hd[16];
#pragma unroll
    for (int k = 0; k < 16; k++) { he[k] = 0ull; hd[k] = 0ull; }

    const float* up = g_u + ((size_t)b * T_) * H_ + lane;
    float*       dp = g_dec + ((size_t)b * T_) * H_ + lane;

    // 4-deep prefetch ring for u (DRAM latency cover)
    float ur[4];
#pragma unroll
    for (int i = 0; i < 4; i++) ur[i] = up[(size_t)i * H_];

    for (int t = 0; t < T_; t += 4) {
#pragma unroll
        for (int i = 0; i < 4; i++) {
            const float u = ur[i];
            const int tn  = t + 4 + i;
            ur[i] = up[(size_t)((tn < T_) ? tn : 0) * H_];

            // decoder recurrent partial (independent of this step's encoder)
            u64 d0 = 0, d1 = 0, d2 = 0, d3 = 0;
#pragma unroll
            for (int k = 0; k < 16; k += 4) {
                d0 = fma2(Wd[k],     hd[k],     d0);
                d1 = fma2(Wd[k + 1], hd[k + 1], d1);
                d2 = fma2(Wd[k + 2], hd[k + 2], d2);
                d3 = fma2(Wd[k + 3], hd[k + 3], d3);
            }
            const float ds = btot + hsum4(d0, d1, d2, d3);

            // encoder matvec
            u64 a0 = 0, a1 = 0, a2 = 0, a3 = 0;
#pragma unroll
            for (int k = 0; k < 16; k += 4) {
                a0 = fma2(We[k],     he[k],     a0);
                a1 = fma2(We[k + 1], he[k + 1], a1);
                a2 = fma2(We[k + 2], he[k + 2], a2);
                a3 = fma2(We[k + 3], he[k + 3], a3);
            }
            const float hE = tanh_fast(u + hsum4(a0, a1, a2, a3));

            // replicate h_enc via smem (in-order STS -> LDS.128 broadcast)
            she[lane] = hE;
            FENCE();
            {
                const ulonglong2* q = reinterpret_cast<const ulonglong2*>(she);
#pragma unroll
                for (int k = 0; k < 8; k++) {
                    ulonglong2 v = q[k];
                    he[2 * k]     = v.x;
                    he[2 * k + 1] = v.y;
                }
            }
            FENCE();
            // v = M h_enc
            u64 m0 = 0, m1 = 0, m2 = 0, m3 = 0;
#pragma unroll
            for (int k = 0; k < 16; k += 4) {
                m0 = fma2(Mm[k],     he[k],     m0);
                m1 = fma2(Mm[k + 1], he[k + 1], m1);
                m2 = fma2(Mm[k + 2], he[k + 2], m2);
                m3 = fma2(Mm[k + 3], he[k + 3], m3);
            }
            const float hD = tanh_fast(ds + hsum4(m0, m1, m2, m3));

            // replicate h_dec
            shd[lane] = hD;
            FENCE();
            dp[(size_t)(t + i) * H_] = hD;
            {
                const ulonglong2* q = reinterpret_cast<const ulonglong2*>(shd);
#pragma unroll
                for (int k = 0; k < 8; k++) {
                    ulonglong2 v = q[k];
                    hd[2 * k]     = v.x;
                    hd[2 * k + 1] = v.y;
                }
            }
            FENCE();
        }
    }
}

// ---------------- Kernel 3: out = dec @ W_ro^T + b_ro ----------------
// Tiled: 128 rows/tile of g_dec staged in smem, one sync per tile.
#define K3_TILE 128
#define K3_NT   (R_ / K3_TILE)     // 4096
#define K3_GRID 2048
__global__ void __launch_bounds__(256) k_proj_out(const float* __restrict__ Wro,
                                                  const float* __restrict__ bro,
                                                  float* __restrict__ out) {
    __shared__ __align__(16) float4 sh[2][K3_TILE * H_ / 4];    // 2 x 16KB
    const int tid  = threadIdx.x;
    const int lane = tid & 31;
    const int w    = tid >> 5;

    // lane handles output dims lane and lane+32
    u64 W0[16], W1[16];
    {
        const u64* r0 = reinterpret_cast<const u64*>(Wro + lane * H_);
        const u64* r1 = reinterpret_cast<const u64*>(Wro + (lane + 32) * H_);
#pragma unroll
        for (int k = 0; k < 16; k++) { W0[k] = r0[k]; W1[k] = r1[k]; }
    }
    const float c0 = bro[lane];
    const float c1 = bro[lane + 32];

    const float4* d4 = reinterpret_cast<const float4*>(g_dec);

    int tile = blockIdx.x;
    {
        const float4* src = d4 + (size_t)tile * (K3_TILE * H_ / 4);
#pragma unroll
        for (int k = 0; k < 4; k++) sh[0][tid + k * 256] = src[tid + k * 256];
    }
    __syncthreads();

    int p = 0;
    while (tile < K3_NT) {
        const int nt = tile + K3_GRID;
        float4 n0, n1, n2, n3;
        if (nt < K3_NT) {
            const float4* src = d4 + (size_t)nt * (K3_TILE * H_ / 4);
            n0 = src[tid];       n1 = src[tid + 256];
            n2 = src[tid + 512]; n3 = src[tid + 768];
        }
#pragma unroll
        for (int r = 0; r < 16; r++) {
            const int lrow = w * 16 + r;
            const ulonglong2* hp =
                reinterpret_cast<const ulonglong2*>(&sh[p][lrow * (H_ / 4)]);
            u64 a0 = 0, a1 = 0, b0 = 0, b1 = 0;
#pragma unroll
            for (int k = 0; k < 8; k++) {
                ulonglong2 v = hp[k];
                a0 = fma2(W0[2 * k],     v.x, a0);
                a1 = fma2(W0[2 * k + 1], v.y, a1);
                b0 = fma2(W1[2 * k],     v.x, b0);
                b1 = fma2(W1[2 * k + 1], v.y, b1);
            }
            const size_t row = (size_t)tile * K3_TILE + lrow;
            out[row * DIN + lane]      = c0 + unpack_sum(add2(a0, a1));
            out[row * DIN + 32 + lane] = c1 + unpack_sum(add2(b0, b1));
        }
        if (nt < K3_NT) {
            sh[p ^ 1][tid]       = n0; sh[p ^ 1][tid + 256] = n1;
            sh[p ^ 1][tid + 512] = n2; sh[p ^ 1][tid + 768] = n3;
        }
        __syncthreads();
        p ^= 1;
        tile = nt;
    }
}

// ---------------- launch ----------------
extern "C" void kernel_launch(void* const* d_in, const int* in_sizes, int n_in,
                              void* d_out, int out_size) {
    const float* x     = (const float*)d_in[0];
    const float* Win   = (const float*)d_in[1];
    const float* bin   = (const float*)d_in[2];
    const float* Wrese = (const float*)d_in[3];
    const float* brese = (const float*)d_in[4];
    const float* Wcode = (const float*)d_in[5];
    const float* bcode = (const float*)d_in[6];
    const float* Wco   = (const float*)d_in[7];
    const float* bco   = (const float*)d_in[8];
    const float* Wresd = (const float*)d_in[9];
    const float* bresd = (const float*)d_in[10];
    const float* Wro   = (const float*)d_in[11];
    const float* bro   = (const float*)d_in[12];
    float* out = (float*)d_out;

    k_proj_in<<<K1_GRID, 256>>>(x, Win, bin, brese);
    k_scan<<<B_, 32>>>(Wrese, Wresd, Wcode, bcode, Wco, bco, bresd);
    k_proj_out<<<K3_GRID, 256>>>(Wro, bro, out);
}